// round 2
// baseline (speedup 1.0000x reference)
#include <cuda_runtime.h>

// Encoder_82910048682485 — R2: packed f32x2 FMA + 2 CTAs/SM + cp.async
// double-buffered weight slabs.
//
// Level structure: children of parents [p0, p0+n) are the contiguous slab
// [2p0+1, 2p0+2n] -> each level is a fused 2-layer MLP on contiguous memory.
//
// Per-level kernel (template BM rows/block, 256 threads):
//   sX [BM][260]  : X tile, later overwritten with H (layer-1 output)
//   sW [2][16][256]: double-buffered weight slabs (BK=16 k-rows)
//   Layer1 accumulators (both 128-col chunks) live entirely in registers
//   (2 x RPT x 4 f32x2), so no separate H smem buffer -> 97KB smem -> 2 CTAs/SM.
//   All FMAs are fma.rn.f32x2 (2 columns per issue).

using ull = unsigned long long;

static __forceinline__ __device__ float lrelu(float v) {
    return v > 0.0f ? v : 0.01f * v;
}

static __forceinline__ __device__ ull pack2(float x) {
    ull r; asm("mov.b64 %0, {%1, %1};" : "=l"(r) : "f"(x)); return r;
}
static __forceinline__ __device__ ull pack2(float x, float y) {
    ull r; asm("mov.b64 %0, {%1, %2};" : "=l"(r) : "f"(x), "f"(y)); return r;
}
static __forceinline__ __device__ void unpack2(ull v, float& x, float& y) {
    asm("mov.b64 {%0, %1}, %2;" : "=f"(x), "=f"(y) : "l"(v));
}
static __forceinline__ __device__ void ffma2(ull& d, ull a, ull b) {
    asm("fma.rn.f32x2 %0, %1, %2, %0;" : "+l"(d) : "l"(a), "l"(b));
}
static __forceinline__ __device__ void lds_v2u64(unsigned addr, ull& a, ull& b) {
    asm volatile("ld.shared.v2.u64 {%0, %1}, [%2];" : "=l"(a), "=l"(b) : "r"(addr));
}
static __forceinline__ __device__ void cp16(unsigned dst, const void* src) {
    asm volatile("cp.async.cg.shared.global [%0], [%1], 16;" :: "r"(dst), "l"(src));
}
#define CP_COMMIT() asm volatile("cp.async.commit_group;")
#define CP_WAIT0()  asm volatile("cp.async.wait_group 0;")

constexpr int DEPTH = 18;

template<int BM>
__global__ void __launch_bounds__(256, 2)
mlp_level_kernel(const float* __restrict__ X, float* __restrict__ Y,
                 const float* __restrict__ W1, const float* __restrict__ b1,
                 const float* __restrict__ W2, const float* __restrict__ b2,
                 int n)
{
    constexpr int RPT = BM / 16;                 // rows per thread
    extern __shared__ float smem[];
    float* sX = smem;                            // [BM][260]
    float* sW = smem + BM * 260;                 // [2][16][256]

    const int tid  = threadIdx.x;
    const int tx   = tid & 15;                   // 16 col groups of 8 (within 128-chunk)
    const int ty   = tid >> 4;                   // 16 row groups of RPT
    const int row0 = blockIdx.x * BM;

    const unsigned sW_base = (unsigned)__cvta_generic_to_shared(sW);

    // ---- prologue: async-load W1 slab 0 into buf 0 (overlaps X-tile load) ----
    {
        const char* src = (const char*)W1 + (size_t)tid * 16;
        unsigned dst = sW_base + tid * 16;
        #pragma unroll
        for (int j = 0; j < 4; ++j) cp16(dst + j * 4096, src + j * 4096);
        CP_COMMIT();
    }

    // ---- X tile [BM,256] (zero-fill rows >= n) ----
    for (int idx = tid; idx < BM * 64; idx += 256) {
        int r = idx >> 6, c4 = idx & 63;
        float4 v = make_float4(0.f, 0.f, 0.f, 0.f);
        if (row0 + r < n)
            v = reinterpret_cast<const float4*>(X)[(size_t)(row0 + r) * 64 + c4];
        *reinterpret_cast<float4*>(&sX[r * 260 + c4 * 4]) = v;
    }

    // ---- layer-1 accumulators: both 128-col chunks, in registers ----
    ull acc[2][RPT][4];
    #pragma unroll
    for (int c = 0; c < 2; ++c) {
        float4 v0 = *reinterpret_cast<const float4*>(b1 + c * 128 + tx * 8);
        float4 v1 = *reinterpret_cast<const float4*>(b1 + c * 128 + tx * 8 + 4);
        #pragma unroll
        for (int i = 0; i < RPT; ++i) {
            acc[c][i][0] = pack2(v0.x, v0.y);
            acc[c][i][1] = pack2(v0.z, v0.w);
            acc[c][i][2] = pack2(v1.x, v1.y);
            acc[c][i][3] = pack2(v1.z, v1.w);
        }
    }

    int buf = 0;
    // ---- layer 1: 16 slabs of BK=16 over K=256 ----
    for (int s = 0; s < 16; ++s) {
        CP_WAIT0();
        __syncthreads();
        {   // prefetch next slab into buf^1 (slab 15 prefetches W2 slab 0)
            unsigned dstb = sW_base + (buf ^ 1) * 16384 + tid * 16;
            if (s < 15) {
                const char* src = (const char*)W1 + (size_t)(s + 1) * 16384 + tid * 16;
                #pragma unroll
                for (int j = 0; j < 4; ++j) cp16(dstb + j * 4096, src + j * 4096);
            } else {
                const char* src = (const char*)W2 + (size_t)tid * 16;
                #pragma unroll
                for (int j = 0; j < 2; ++j) cp16(dstb + j * 4096, src + j * 4096);
            }
            CP_COMMIT();
        }
        const int kbase = s * 16;
        #pragma unroll
        for (int kk = 0; kk < 16; ++kk) {
            ull apk[RPT];
            #pragma unroll
            for (int i = 0; i < RPT; ++i)
                apk[i] = pack2(sX[(ty * RPT + i) * 260 + kbase + kk]);
            unsigned wrow = sW_base + buf * 16384 + kk * 1024 + tx * 32;
            ull w00, w01, w02, w03, w10, w11, w12, w13;
            lds_v2u64(wrow,        w00, w01);
            lds_v2u64(wrow + 16,   w02, w03);
            lds_v2u64(wrow + 512,  w10, w11);
            lds_v2u64(wrow + 528,  w12, w13);
            #pragma unroll
            for (int i = 0; i < RPT; ++i) {
                ffma2(acc[0][i][0], apk[i], w00);
                ffma2(acc[0][i][1], apk[i], w01);
                ffma2(acc[0][i][2], apk[i], w02);
                ffma2(acc[0][i][3], apk[i], w03);
                ffma2(acc[1][i][0], apk[i], w10);
                ffma2(acc[1][i][1], apk[i], w11);
                ffma2(acc[1][i][2], apk[i], w12);
                ffma2(acc[1][i][3], apk[i], w13);
            }
        }
        buf ^= 1;
    }

    // ---- H = lrelu(acc) overwrites sX (X rows only touched by same ty-group) ----
    __syncthreads();
    #pragma unroll
    for (int c = 0; c < 2; ++c)
        #pragma unroll
        for (int i = 0; i < RPT; ++i) {
            float4 o0, o1; float x, y;
            unpack2(acc[c][i][0], x, y); o0.x = lrelu(x); o0.y = lrelu(y);
            unpack2(acc[c][i][1], x, y); o0.z = lrelu(x); o0.w = lrelu(y);
            unpack2(acc[c][i][2], x, y); o1.x = lrelu(x); o1.y = lrelu(y);
            unpack2(acc[c][i][3], x, y); o1.z = lrelu(x); o1.w = lrelu(y);
            float* p = &sX[(ty * RPT + i) * 260 + c * 128 + tx * 8];
            *reinterpret_cast<float4*>(p)     = o0;
            *reinterpret_cast<float4*>(p + 4) = o1;
        }
    // visibility of H across threads is covered by the sync at top of layer-2 s=0

    // ---- layer-2 accumulators ----
    ull acc2[RPT][4];
    {
        float4 v0 = *reinterpret_cast<const float4*>(b2 + tx * 8);
        float4 v1 = *reinterpret_cast<const float4*>(b2 + tx * 8 + 4);
        #pragma unroll
        for (int i = 0; i < RPT; ++i) {
            acc2[i][0] = pack2(v0.x, v0.y);
            acc2[i][1] = pack2(v0.z, v0.w);
            acc2[i][2] = pack2(v1.x, v1.y);
            acc2[i][3] = pack2(v1.z, v1.w);
        }
    }

    // ---- layer 2: 16 slabs of BK=16 over K=256, N=128 ----
    for (int s = 0; s < 16; ++s) {
        CP_WAIT0();
        __syncthreads();
        if (s < 15) {
            unsigned dstb = sW_base + (buf ^ 1) * 16384 + tid * 16;
            const char* src = (const char*)W2 + (size_t)(s + 1) * 8192 + tid * 16;
            #pragma unroll
            for (int j = 0; j < 2; ++j) cp16(dstb + j * 4096, src + j * 4096);
            CP_COMMIT();
        }
        const int kbase = s * 16;
        #pragma unroll
        for (int kk = 0; kk < 16; ++kk) {
            ull apk[RPT];
            #pragma unroll
            for (int i = 0; i < RPT; ++i)
                apk[i] = pack2(sX[(ty * RPT + i) * 260 + kbase + kk]);
            unsigned wrow = sW_base + buf * 16384 + kk * 512 + tx * 32;
            ull w0, w1, w2, w3;
            lds_v2u64(wrow,      w0, w1);
            lds_v2u64(wrow + 16, w2, w3);
            #pragma unroll
            for (int i = 0; i < RPT; ++i) {
                ffma2(acc2[i][0], apk[i], w0);
                ffma2(acc2[i][1], apk[i], w1);
                ffma2(acc2[i][2], apk[i], w2);
                ffma2(acc2[i][3], apk[i], w3);
            }
        }
        buf ^= 1;
    }

    // ---- store Y = lrelu(acc2) ----
    #pragma unroll
    for (int i = 0; i < RPT; ++i) {
        int r = row0 + ty * RPT + i;
        if (r < n) {
            float4 o0, o1; float x, y;
            unpack2(acc2[i][0], x, y); o0.x = lrelu(x); o0.y = lrelu(y);
            unpack2(acc2[i][1], x, y); o0.z = lrelu(x); o0.w = lrelu(y);
            unpack2(acc2[i][2], x, y); o1.x = lrelu(x); o1.y = lrelu(y);
            unpack2(acc2[i][3], x, y); o1.z = lrelu(x); o1.w = lrelu(y);
            float* p = Y + (size_t)r * 128 + tx * 8;
            *reinterpret_cast<float4*>(p)     = o0;
            *reinterpret_cast<float4*>(p + 4) = o1;
        }
    }
}

constexpr int SMEM64 = 64 * 260 * 4 + 2 * 16 * 256 * 4;   // 99328
constexpr int SMEM16 = 16 * 260 * 4 + 2 * 16 * 256 * 4;   // 49408

// Leaf embedder: Y[i] = lrelu(L[i,:32] @ We + be). 64 rows/block, K=32.
__global__ void __launch_bounds__(256, 1) leaf_kernel(
    const float* __restrict__ L, const float* __restrict__ We,
    const float* __restrict__ be, float* __restrict__ Y)
{
    __shared__ float sL[64 * 36];
    __shared__ float sW[32 * 128];

    const int tid = threadIdx.x;
    const int tx = tid & 15;
    const int ty = tid >> 4;
    const size_t row0 = (size_t)blockIdx.x * 64;

    for (int idx = tid; idx < 512; idx += 256) {
        int r = idx >> 3, c4 = idx & 7;
        float4 v = reinterpret_cast<const float4*>(L + (row0 + r) * 32)[c4];
        *reinterpret_cast<float4*>(&sL[r * 36 + c4 * 4]) = v;
    }
    for (int idx = tid; idx < 1024; idx += 256)
        reinterpret_cast<float4*>(sW)[idx] = reinterpret_cast<const float4*>(We)[idx];
    __syncthreads();

    ull acc[4][4];
    {
        float4 v0 = *reinterpret_cast<const float4*>(be + tx * 8);
        float4 v1 = *reinterpret_cast<const float4*>(be + tx * 8 + 4);
        #pragma unroll
        for (int i = 0; i < 4; ++i) {
            acc[i][0] = pack2(v0.x, v0.y);
            acc[i][1] = pack2(v0.z, v0.w);
            acc[i][2] = pack2(v1.x, v1.y);
            acc[i][3] = pack2(v1.z, v1.w);
        }
    }
    const unsigned sW_base = (unsigned)__cvta_generic_to_shared(sW);
    #pragma unroll
    for (int k = 0; k < 32; ++k) {
        unsigned wrow = sW_base + k * 512 + tx * 32;
        ull w0, w1, w2, w3;
        lds_v2u64(wrow,      w0, w1);
        lds_v2u64(wrow + 16, w2, w3);
        #pragma unroll
        for (int i = 0; i < 4; ++i) {
            ull a = pack2(sL[(ty * 4 + i) * 36 + k]);
            ffma2(acc[i][0], a, w0);
            ffma2(acc[i][1], a, w1);
            ffma2(acc[i][2], a, w2);
            ffma2(acc[i][3], a, w3);
        }
    }
    #pragma unroll
    for (int i = 0; i < 4; ++i) {
        size_t r = row0 + ty * 4 + i;
        float4 o0, o1; float x, y;
        unpack2(acc[i][0], x, y); o0.x = lrelu(x); o0.y = lrelu(y);
        unpack2(acc[i][1], x, y); o0.z = lrelu(x); o0.w = lrelu(y);
        unpack2(acc[i][2], x, y); o1.x = lrelu(x); o1.y = lrelu(y);
        unpack2(acc[i][3], x, y); o1.z = lrelu(x); o1.w = lrelu(y);
        reinterpret_cast<float4*>(Y + r * 128 + tx * 8)[0] = o0;
        reinterpret_cast<float4*>(Y + r * 128 + tx * 8)[1] = o1;
    }
}

extern "C" void kernel_launch(void* const* d_in, const int* in_sizes, int n_in,
                              void* d_out, int out_size)
{
    const float* leaf = (const float*)d_in[0];
    const float* We   = (const float*)d_in[1];
    const float* be   = (const float*)d_in[2];
    const float* W1   = (const float*)d_in[3];
    const float* b1   = (const float*)d_in[4];
    const float* W2   = (const float*)d_in[5];
    const float* b2   = (const float*)d_in[6];
    float* out = (float*)d_out;

    cudaFuncSetAttribute(mlp_level_kernel<64>,
                         cudaFuncAttributeMaxDynamicSharedMemorySize, SMEM64);
    cudaFuncSetAttribute(mlp_level_kernel<16>,
                         cudaFuncAttributeMaxDynamicSharedMemorySize, SMEM16);

    const size_t leaf_start = (size_t)(1u << DEPTH) - 1;
    leaf_kernel<<<(1 << DEPTH) / 64, 256>>>(leaf, We, be, out + leaf_start * 128);

    for (int l = DEPTH - 1; l >= 0; --l) {
        const int n = 1 << l;
        const size_t p0 = (size_t)(1u << l) - 1;
        const float* X = out + (2 * p0 + 1) * 128;
        float* Y = out + p0 * 128;
        if (n >= 16384) {
            mlp_level_kernel<64><<<n / 64, 256, SMEM64>>>(X, Y, W1, b1, W2, b2, n);
        } else {
            mlp_level_kernel<16><<<(n + 15) / 16, 256, SMEM16>>>(X, Y, W1, b1, W2, b2, n);
        }
    }
}